// round 7
// baseline (speedup 1.0000x reference)
#include <cuda_runtime.h>
#include <math.h>

#define NB 256
#define S  4096
#define FO 8
#define NM 64
#define FM 6
#define EPSF 1e-5f

#define PBLK 16     // proc stats sub-blocks per instance (4096 float4 each)
#define OSB  4      // opes stats sub-blocks per instance (1024 rows each)
#define NPB  32     // proc norm sub-blocks per instance (2048 float4 each)
#define OPB  8      // opes norm sub-blocks per instance (1024 float4 each)

// -------- device scratch (fixed slots, overwritten every replay; no atomics) --------
__device__ float g_part[NB][PBLK][4];        // proc partials: sum, sumsq, nnz
__device__ float g_opart[NB][OSB][2][FO];    // opes partials: [0]=sum, [1]=sumsq
__device__ float g_mmean[NB * FM];
__device__ float g_mrstd[NB * FM];

__device__ __forceinline__ float warp_sum(float v) {
#pragma unroll
    for (int o = 16; o > 0; o >>= 1) v += __shfl_down_sync(0xffffffffu, v, o);
    return v;
}

// ==================== Kernel A: all statistics ====================
// blocks [0, NB*OSB)              : opes masked partials (short, scheduled first)
// blocks [NB*OSB, NB*OSB+NB*PBLK) : proc partials
__global__ void __launch_bounds__(256)
statsA_k(const float4* __restrict__ pt,
         const float* __restrict__ opes, const float* __restrict__ mas,
         const int* __restrict__ nums) {
    const int bid = blockIdx.x;

    if (bid < NB * OSB) {
        // ---------------- opes partials (rows [sub*1024, sub*1024+1024) ∩ [0,n)) ----------------
        const int b   = bid >> 2;
        const int sub = bid & (OSB - 1);
        const int n   = nums[b];
        const int r0  = sub * 1024;
        const int r1  = min(r0 + 1024, n);

        float s[FO], q[FO];
#pragma unroll
        for (int f = 0; f < FO; f++) { s[f] = 0.f; q[f] = 0.f; }

        const float4* op = (const float4*)(opes + (size_t)b * S * FO);
        for (int r = r0 + threadIdx.x; r < r1; r += 256) {
            float4 a  = __ldcs(&op[r * 2]);
            float4 b4 = __ldcs(&op[r * 2 + 1]);
            float x[FO] = {a.x, a.y, a.z, a.w, b4.x, b4.y, b4.z, b4.w};
#pragma unroll
            for (int f = 0; f < FO; f++) { s[f] += x[f]; q[f] += x[f] * x[f]; }
        }

        __shared__ float sh[16][8];
        int lane = threadIdx.x & 31, w = threadIdx.x >> 5;
#pragma unroll
        for (int f = 0; f < FO; f++) {
            float rs = warp_sum(s[f]);
            float rq = warp_sum(q[f]);
            if (lane == 0) { sh[f][w] = rs; sh[f + 8][w] = rq; }
        }
        __syncthreads();

        if (threadIdx.x < FO) {
            int f = threadIdx.x;
            float ts = 0.f, tq = 0.f;
#pragma unroll
            for (int i = 0; i < 8; i++) { ts += sh[f][i]; tq += sh[f + 8][i]; }
            g_opart[b][sub][0][f] = ts;
            g_opart[b][sub][1][f] = tq;
        }

        // mas stats on sub-0's spare warp (always has work: n >= 16)
        if (sub == 0 && threadIdx.x >= 64 && threadIdx.x < 64 + FM) {
            int f = threadIdx.x - 64;
            const float* mp = mas + (size_t)b * NM * FM + f;
            float ts = 0.f, tq = 0.f;
#pragma unroll
            for (int m = 0; m < NM; m++) { float x = mp[m * FM]; ts += x; tq += x * x; }
            float fm   = (float)NM;
            float mean = ts / fm;
            float var  = (tq - ts * ts / fm) / (fm - 1.f);
            g_mmean[b * FM + f] = mean;
            g_mrstd[b * FM + f] = 1.f / (sqrtf(var) + EPSF);
        }
    } else {
        // ---------------- proc partials ----------------
        const int pb  = bid - NB * OSB;
        const int b   = pb >> 4;
        const int sub = pb & (PBLK - 1);
        const float4* src = pt + (size_t)b * (S * NM / 4) + (size_t)sub * 4096;

        float s = 0.f, ss = 0.f, c = 0.f;
        for (int i0 = threadIdx.x; i0 < 4096; i0 += 1024) {
            float4 v[4];
#pragma unroll
            for (int k = 0; k < 4; k++) v[k] = __ldcs(&src[i0 + k * 256]);
#pragma unroll
            for (int k = 0; k < 4; k++) {
                s  += (v[k].x + v[k].y) + (v[k].z + v[k].w);
                ss += (v[k].x * v[k].x + v[k].y * v[k].y) + (v[k].z * v[k].z + v[k].w * v[k].w);
                c  += (float)((v[k].x != 0.f) + (v[k].y != 0.f) + (v[k].z != 0.f) + (v[k].w != 0.f));
            }
        }

        __shared__ float sh2[3][8];
        int lane = threadIdx.x & 31, w = threadIdx.x >> 5;
        s = warp_sum(s); ss = warp_sum(ss); c = warp_sum(c);
        if (lane == 0) { sh2[0][w] = s; sh2[1][w] = ss; sh2[2][w] = c; }
        __syncthreads();
        if (threadIdx.x == 0) {
            float ts = 0.f, tss = 0.f, tc = 0.f;
#pragma unroll
            for (int i = 0; i < 8; i++) { ts += sh2[0][i]; tss += sh2[1][i]; tc += sh2[2][i]; }
            g_part[b][sub][0] = ts;
            g_part[b][sub][1] = tss;
            g_part[b][sub][2] = tc;
        }
    }
}

// ==================== Kernel B: all normalization ====================
// blocks [0, NB*NPB)             : proc normalize
// blocks [+, NB*OPB)             : opes normalize (combines 4 partials in prologue)
// blocks [+, 384)                : mas normalize
__global__ void __launch_bounds__(256)
normB_k(const float4* __restrict__ pt, float4* __restrict__ out_proc,
        const float4* __restrict__ opes4, float4* __restrict__ out_opes,
        const float* __restrict__ mas, float* __restrict__ out_mas,
        const int* __restrict__ nums) {
    const int bid = blockIdx.x;

    if (bid < NB * NPB) {
        // ---------------- proc normalize ----------------
        const int b   = bid >> 5;
        const int sub = bid & (NPB - 1);

        __shared__ float sm, sr;
        if (threadIdx.x < 32) {
            int lane = threadIdx.x;
            float s = 0.f, ss = 0.f, c = 0.f;
            if (lane < PBLK) {
                s  = g_part[b][lane][0];
                ss = g_part[b][lane][1];
                c  = g_part[b][lane][2];
            }
#pragma unroll
            for (int o = 8; o > 0; o >>= 1) {
                s  += __shfl_down_sync(0xffffffffu, s, o);
                ss += __shfl_down_sync(0xffffffffu, ss, o);
                c  += __shfl_down_sync(0xffffffffu, c, o);
            }
            if (lane == 0) {
                float m   = s / c;
                float var = (ss - s * s / c) / (c - 1.f);
                sm = m;
                sr = 1.f / (sqrtf(var) + EPSF);
            }
        }
        __syncthreads();
        const float m = sm, r = sr;

        const size_t base = (size_t)b * (S * NM / 4) + (size_t)sub * 2048;
        const float4* src = pt + base;
        float4*       dst = out_proc + base;
        for (int i0 = threadIdx.x; i0 < 2048; i0 += 512) {
            float4 v0 = __ldcs(&src[i0]);
            float4 v1 = __ldcs(&src[i0 + 256]);
            float4 o0, o1;
            o0.x = (v0.x != 0.f) ? (v0.x - m) * r : 0.f;
            o0.y = (v0.y != 0.f) ? (v0.y - m) * r : 0.f;
            o0.z = (v0.z != 0.f) ? (v0.z - m) * r : 0.f;
            o0.w = (v0.w != 0.f) ? (v0.w - m) * r : 0.f;
            o1.x = (v1.x != 0.f) ? (v1.x - m) * r : 0.f;
            o1.y = (v1.y != 0.f) ? (v1.y - m) * r : 0.f;
            o1.z = (v1.z != 0.f) ? (v1.z - m) * r : 0.f;
            o1.w = (v1.w != 0.f) ? (v1.w - m) * r : 0.f;
            __stcs(&dst[i0], o0);
            __stcs(&dst[i0 + 256], o1);
        }
    } else if (bid < NB * NPB + NB * OPB) {
        // ---------------- opes normalize ----------------
        const int obid = bid - NB * NPB;
        const int b    = obid >> 3;
        const int base = b * 8192 + (obid & (OPB - 1)) * 1024;

        __shared__ float mm[FO], rr[FO];
        if (threadIdx.x < FO) {
            const int f = threadIdx.x;
            float ts = 0.f, tq = 0.f;
#pragma unroll
            for (int s2 = 0; s2 < OSB; s2++) {
                ts += g_opart[b][s2][0][f];
                tq += g_opart[b][s2][1][f];
            }
            float fn  = (float)nums[b];
            float mean = ts / fn;
            float var  = (tq - ts * ts / fn) / (fn - 1.f);
            mm[f] = mean;
            rr[f] = 1.f / (sqrtf(var) + EPSF);
        }
        __syncthreads();

        for (int i0 = threadIdx.x; i0 < 1024; i0 += 512) {
            float4 v0 = __ldcs(&opes4[base + i0]);
            float4 v1 = __ldcs(&opes4[base + i0 + 256]);
            const float* M0 = &mm[(i0 & 1) * 4];
            const float* R0 = &rr[(i0 & 1) * 4];
            const float* M1 = &mm[((i0 + 256) & 1) * 4];
            const float* R1 = &rr[((i0 + 256) & 1) * 4];
            float4 o0, o1;
            o0.x = (v0.x - M0[0]) * R0[0];
            o0.y = (v0.y - M0[1]) * R0[1];
            o0.z = (v0.z - M0[2]) * R0[2];
            o0.w = (v0.w - M0[3]) * R0[3];
            o1.x = (v1.x - M1[0]) * R1[0];
            o1.y = (v1.y - M1[1]) * R1[1];
            o1.z = (v1.z - M1[2]) * R1[2];
            o1.w = (v1.w - M1[3]) * R1[3];
            __stcs(&out_opes[base + i0], o0);
            __stcs(&out_opes[base + i0 + 256], o1);
        }
    } else {
        // ---------------- mas normalize ----------------
        const int mbid = bid - NB * NPB - NB * OPB;
        const int i = mbid * 256 + threadIdx.x;
        const int N = NB * NM * FM;
        if (i < N) {
            int b = i / (NM * FM);
            int f = i % FM;
            out_mas[i] = (mas[i] - g_mmean[b * FM + f]) * g_mrstd[b * FM + f];
        }
    }
}

extern "C" void kernel_launch(void* const* d_in, const int* in_sizes, int n_in,
                              void* d_out, int out_size) {
    const float* raw_opes = (const float*)d_in[0];
    const float* raw_mas  = (const float*)d_in[1];
    const float* proc     = (const float*)d_in[2];
    const int*   nums     = (const int*)d_in[3];

    float* out_opes = (float*)d_out;
    float* out_mas  = out_opes + (size_t)NB * S * FO;
    float* out_proc = out_mas  + (size_t)NB * NM * FM;

    const int gridA = NB * OSB + NB * PBLK;                               // 1024 + 4096
    const int gridB = NB * NPB + NB * OPB + (NB * NM * FM + 255) / 256;   // 8192+2048+384

    statsA_k<<<gridA, 256>>>((const float4*)proc, raw_opes, raw_mas, nums);
    normB_k<<<gridB, 256>>>((const float4*)proc, (float4*)out_proc,
                            (const float4*)raw_opes, (float4*)out_opes,
                            raw_mas, out_mas, nums);
}